// round 17
// baseline (speedup 1.0000x reference)
#include <cuda_runtime.h>
#include <cstdint>

// Problem constants
#define T_STEPS 512
#define BATCH   32
#define DIM     512
#define HID     256
#define A1N     16
#define A2N     128

typedef unsigned long long ull;

// ---------------- device scratch (allocation-free rule: __device__ globals) ----
__device__ float g_lut[8200];                    // exp(f(x)) lookup table
__device__ float g_seq[T_STEPS * BATCH];         // stage-1 output (T,B)
__device__ float g_hs [T_STEPS * BATCH * HID];   // LSTM hidden history (T,B,H)
__device__ float g_s2 [T_STEPS * BATCH];         // stage-3 logits (T,B)

// =============================================================================
// K0: build LUT  g(x) = exp( sum_a u1[a] * tanh(x*W1[a] + b1[a]) ),  x in [-8,8]
// =============================================================================
__global__ void k0_lut(const float* __restrict__ W1,
                       const float* __restrict__ b1,
                       const float* __restrict__ u1) {
    int i = blockIdx.x * blockDim.x + threadIdx.x;
    if (i > 8192) return;
    float x = -8.f + (float)i * (16.f / 8192.f);
    float f = 0.f;
#pragma unroll
    for (int a = 0; a < A1N; a++)
        f += u1[a] * tanhf(x * W1[a] + b1[a]);
    g_lut[i] = expf(f);
}

// =============================================================================
// K1: AttLayer1 soft pool over D.  seq[t,b] = sum_d x*g(x) / sum_d g(x)
// =============================================================================
__global__ __launch_bounds__(256) void k1_att1(const float* __restrict__ x) {
    __shared__ float lut[8193];
    for (int i = threadIdx.x; i < 8193; i += 256) lut[i] = g_lut[i];
    __syncthreads();

    int warp = threadIdx.x >> 5, lane = threadIdx.x & 31;
#pragma unroll
    for (int q = 0; q < 4; q++) {
        int pair = blockIdx.x * 32 + warp * 4 + q;     // pair = t*B + b
        const float* xp = x + (size_t)pair * DIM;
        float aw = 0.f, axw = 0.f;
#pragma unroll 4
        for (int d = lane; d < DIM; d += 32) {
            float v = xp[d];
            float pos = (v + 8.f) * 512.f;
            pos = fminf(fmaxf(pos, 0.f), 8191.0f);
            int   i0 = (int)pos;
            float fr = pos - (float)i0;
            float g0 = lut[i0], g1 = lut[i0 + 1];
            float g  = g0 + fr * (g1 - g0);
            aw  += g;
            axw += v * g;
        }
#pragma unroll
        for (int o = 16; o > 0; o >>= 1) {
            aw  += __shfl_xor_sync(0xFFFFFFFFu, aw,  o);
            axw += __shfl_xor_sync(0xFFFFFFFFu, axw, o);
        }
        if (lane == 0) g_seq[pair] = axw / aw;
    }
}

// =============================================================================
// K_NOP: profiling-slot alignment dummy (keeps ncu capture slot on k2)
// =============================================================================
__global__ void k_nop() {}

// =============================================================================
// K2: LSTM recurrence.  8 clusters x 8 CTAs, 4 batches/cluster in FOUR groups
// of ONE batch each, with FOUR dedicated updater warps (R10 layout + R11 fix).
// Block = 384: warps 0-7 GEMV+activation (broadcast LDS, l=tid&127, kh=tid>>7),
// warps 8-11 = per-group updaters (independent chains, pipelined against the
// GEMV warps' 4 program-order segments).
// Barriers: psum = id 1+g (blocking, reusable), act-ready = id 5+g*2+ph.
// =============================================================================
__device__ __forceinline__ unsigned smem_u32(const void* p) {
    unsigned a;
    asm("{ .reg .u64 t; cvta.to.shared.u64 t, %1; cvt.u32.u64 %0, t; }"
        : "=r"(a) : "l"(p));
    return a;
}

__device__ __forceinline__ float fsigmoid(float x) {
    return __fdividef(1.f, 1.f + __expf(-x));
}
__device__ __forceinline__ float ftanh(float x) {
    return __fdividef(2.f, 1.f + __expf(-2.f * x)) - 1.f;
}

// poll all 8 u32 flags >= tgt with two vector acquire loads (R14-proven)
__device__ __forceinline__ void poll_flags(unsigned fl_addr, unsigned tgt) {
    for (;;) {
        unsigned f0, f1, f2, f3, f4, f5, f6, f7;
        asm volatile("ld.acquire.cluster.shared::cta.v4.u32 {%0,%1,%2,%3}, [%4];"
                     : "=r"(f0), "=r"(f1), "=r"(f2), "=r"(f3)
                     : "r"(fl_addr) : "memory");
        asm volatile("ld.acquire.cluster.shared::cta.v4.u32 {%0,%1,%2,%3}, [%4];"
                     : "=r"(f4), "=r"(f5), "=r"(f6), "=r"(f7)
                     : "r"(fl_addr + 16) : "memory");
        unsigned m = min(min(min(f0, f1), min(f2, f3)),
                         min(min(f4, f5), min(f6, f7)));
        if (m >= tgt) break;
    }
}

#define NTHR 384
#define NACT 288   // act-ready barrier: 8 GEMV warps (256) + 1 updater warp (32)

__global__ void __cluster_dims__(8, 1, 1) __launch_bounds__(NTHR, 1)
k2_lstm(const float* __restrict__ Whh, const float* __restrict__ Wih,
        const float* __restrict__ bih, const float* __restrict__ bhh,
        const float* __restrict__ h0,  const float* __restrict__ c0) {
    // hbuf[g][ph] = 256-float h vector of batch b0g+g as 128 ull k-pairs.
    // CTA rank r's block = floats [32r,32r+32) = bytes [128r, 128r+128).
    __shared__ ull    hbuf[4][2][128];          // 8 KB
    __shared__ float  psum[4][2][2][128];       // [g][ph][kh][row], 8 KB
    __shared__ float  act [4][2][128];          // [g][ph][row], 4 KB
    __shared__ __align__(16) float hloc[4][32]; // staged outgoing h per group
    __shared__ float  sq[4][T_STEPS];           // 8 KB
    __shared__ __align__(16) unsigned flags[4][8];

    const int tid = threadIdx.x;
    unsigned rank;
    asm("mov.u32 %0, %%cluster_ctarank;" : "=r"(rank));
    const int cid = blockIdx.x >> 3;
    const int b0g = cid * 4;

    // ---- common preloads -------------------------------------------------------
    for (int i = tid; i < 4 * T_STEPS; i += NTHR) {
        int bb = i >> 9, tt = i & 511;
        sq[bb][tt] = g_seq[tt * BATCH + b0g + bb];
    }
    for (int i = tid; i < 4 * HID; i += NTHR) {
        int g = i >> 8, U = i & 255;
        ((float*)&hbuf[g][0][0])[U] = h0[(b0g + g) * HID + U];
    }
    if (tid < 32) flags[tid >> 3][tid & 7] = 0;

    const unsigned fl_addr = smem_u32(&flags[0][0]);

    if (tid < 256) {
        // ======================= GEMV role (warps 0-7) ==========================
        const int l  = tid & 127;           // gate row (broadcast-preserving map)
        const int kh = tid >> 7;            // k-half
        const int grow = (l >> 5) * HID + (int)rank * 32 + (l & 31);
        const bool isg = ((l >> 5) == 2);   // g-gate -> tanh

        ull w[64];
        const ull* wrow = reinterpret_cast<const ull*>(Whh) + (size_t)grow * 128 + kh * 64;
#pragma unroll
        for (int j = 0; j < 64; j++) w[j] = wrow[j];

        const float bsum = bih[grow] + bhh[grow];
        const float wih  = Wih[grow];

        __syncthreads();
        asm volatile("barrier.cluster.arrive.aligned;" ::: "memory");
        asm volatile("barrier.cluster.wait.aligned;"   ::: "memory");

        for (int t = 0; t < T_STEPS; t++) {
            const int ph = t & 1;
            const unsigned tgt = (unsigned)t;

#pragma unroll
            for (int g = 0; g < 4; g++) {
                poll_flags(fl_addr + 32u * g, tgt);
                // GEMV: full 128-k half for ONE batch (pairs = adjacent k)
                {
                    const ulonglong2* hp =
                        reinterpret_cast<const ulonglong2*>(&hbuf[g][ph][kh * 64]);
                    ull a0 = 0ULL, a1 = 0ULL;
#pragma unroll
                    for (int j = 0; j < 32; j++) {
                        ulonglong2 h2 = hp[j];
                        asm("fma.rn.f32x2 %0, %1, %2, %0;" : "+l"(a0) : "l"(w[2 * j]),     "l"(h2.x));
                        asm("fma.rn.f32x2 %0, %1, %2, %0;" : "+l"(a1) : "l"(w[2 * j + 1]), "l"(h2.y));
                    }
                    float lo0, hi0, lo1, hi1;
                    asm("mov.b64 {%0,%1}, %2;" : "=f"(lo0), "=f"(hi0) : "l"(a0));
                    asm("mov.b64 {%0,%1}, %2;" : "=f"(lo1), "=f"(hi1) : "l"(a1));
                    psum[g][ph][kh][l] = (lo0 + hi0) + (lo1 + hi1);
                }
                asm volatile("bar.sync %0, %1;" :: "r"(1 + g), "r"(256) : "memory");
                if (kh == 0) {
                    float s = psum[g][ph][0][l] + psum[g][ph][1][l]
                            + bsum + wih * sq[g][t];
                    act[g][ph][l] = isg ? ftanh(s) : fsigmoid(s);
                }
                asm volatile("bar.arrive %0, %1;" :: "r"(5 + g * 2 + ph), "r"(NACT) : "memory");
            }
        }
    } else {
        // ================= updater role: warp 8+g owns group g ==================
        const int g    = (tid - 256) >> 5;          // group 0..3
        const int lane = tid & 31;                  // unit within this CTA
        const int U    = (int)rank * 32 + lane;

        float creg = c0[(b0g + g) * HID + U];

        const unsigned hl_addr = smem_u32(&hloc[g][0]);
        unsigned dst0 = 0, dst1 = 0, dfl = 0;
        if (lane < 8) {
            unsigned base0 = smem_u32(&hbuf[g][0][0]) + (unsigned)rank * 128u;
            unsigned base1 = smem_u32(&hbuf[g][1][0]) + (unsigned)rank * 128u;
            asm("mapa.shared::cluster.u32 %0, %1, %2;" : "=r"(dst0) : "r"(base0), "r"(lane));
            asm("mapa.shared::cluster.u32 %0, %1, %2;" : "=r"(dst1) : "r"(base1), "r"(lane));
            asm("mapa.shared::cluster.u32 %0, %1, %2;"
                : "=r"(dfl) : "r"(fl_addr + 32u * g + 4u * rank), "r"(lane));
        }

        __syncthreads();
        asm volatile("barrier.cluster.arrive.aligned;" ::: "memory");
        asm volatile("barrier.cluster.wait.aligned;"   ::: "memory");

        for (int t = 0; t < T_STEPS; t++) {
            const int ph = t & 1, nph = ph ^ 1;

            asm volatile("bar.sync %0, %1;" :: "r"(5 + g * 2 + ph), "r"(NACT) : "memory");
            float ai = act[g][ph][lane],      af = act[g][ph][32 + lane];
            float ag = act[g][ph][64 + lane], ao = act[g][ph][96 + lane];
            creg = af * creg + ai * ag;
            float hv = ao * ftanh(creg);
            hloc[g][lane] = hv;
            __syncwarp();
            if (lane < 8) {
                unsigned dst = nph ? dst1 : dst0;
#pragma unroll
                for (int j = 0; j < 8; j++) {
                    unsigned r0, r1, r2, r3;
                    asm volatile("ld.shared.v4.b32 {%0,%1,%2,%3}, [%4];"
                                 : "=r"(r0), "=r"(r1), "=r"(r2), "=r"(r3)
                                 : "r"(hl_addr + 16u * j));
                    asm volatile("st.shared::cluster.v4.b32 [%0], {%1,%2,%3,%4};"
                                 :: "r"(dst + 16u * j), "r"(r0), "r"(r1), "r"(r2), "r"(r3)
                                 : "memory");
                }
                asm volatile("st.release.cluster.shared::cluster.u32 [%0], %1;"
                             :: "r"(dfl), "r"((unsigned)(t + 1)) : "memory");
            }
            g_hs[((size_t)t * BATCH + b0g + g) * HID + U] = hv;
            __syncwarp();
        }
    }

    // keep smem alive until all peers' in-flight remote stores complete
    asm volatile("barrier.cluster.arrive.aligned;" ::: "memory");
    asm volatile("barrier.cluster.wait.aligned;"   ::: "memory");
}

// =============================================================================
// K3: AttLayer2 logits.  s2[t,b] = sum_a u2[a]*tanh( hs[t,b,:]@W2[:,a] + b2[a] )
// =============================================================================
__global__ __launch_bounds__(256) void k3_att2(const float* __restrict__ W2,
                                               const float* __restrict__ b2,
                                               const float* __restrict__ u2) {
    __shared__ float sh[128][33];
    __shared__ float sw[32][128];
    __shared__ float sp[128][17];
    __shared__ float sb2[A2N], su2[A2N];

    const int tid = threadIdx.x;
    const int b = blockIdx.x & 31, tq = blockIdx.x >> 5;
    const int t0 = tq * 128;
    if (tid < A2N) { sb2[tid] = b2[tid]; su2[tid] = u2[tid]; }

    const int tx = tid & 15;
    const int ty = tid >> 4;

    ull acc[8][4];
#pragma unroll
    for (int i = 0; i < 8; i++)
#pragma unroll
        for (int p = 0; p < 4; p++) acc[i][p] = 0ULL;

    for (int kc = 0; kc < 8; kc++) {
        __syncthreads();
        for (int idx = tid; idx < 4096; idx += 256) {
            int tl = idx >> 5, k = idx & 31;
            sh[tl][k] = g_hs[((size_t)(t0 + tl) * BATCH + b) * HID + kc * 32 + k];
        }
        for (int idx = tid; idx < 4096; idx += 256) {
            int k = idx >> 7, a = idx & 127;
            sw[k][a] = W2[(kc * 32 + k) * A2N + a];
        }
        __syncthreads();
#pragma unroll 4
        for (int k = 0; k < 32; k++) {
            const ull* wv = reinterpret_cast<const ull*>(&sw[k][tx * 8]);
            ull w0 = wv[0], w1 = wv[1], w2_ = wv[2], w3 = wv[3];
#pragma unroll
            for (int i = 0; i < 8; i++) {
                float hvv = sh[ty * 8 + i][k];
                ull hh;
                asm("mov.b64 %0, {%1,%1};" : "=l"(hh) : "f"(hvv));
                asm("fma.rn.f32x2 %0, %1, %2, %0;" : "+l"(acc[i][0]) : "l"(w0),  "l"(hh));
                asm("fma.rn.f32x2 %0, %1, %2, %0;" : "+l"(acc[i][1]) : "l"(w1),  "l"(hh));
                asm("fma.rn.f32x2 %0, %1, %2, %0;" : "+l"(acc[i][2]) : "l"(w2_), "l"(hh));
                asm("fma.rn.f32x2 %0, %1, %2, %0;" : "+l"(acc[i][3]) : "l"(w3),  "l"(hh));
            }
        }
    }
    float sres[8];
#pragma unroll
    for (int i = 0; i < 8; i++) sres[i] = 0.f;
#pragma unroll
    for (int i = 0; i < 8; i++) {
#pragma unroll
        for (int p = 0; p < 4; p++) {
            float lo, hi;
            asm("mov.b64 {%0,%1}, %2;" : "=f"(lo), "=f"(hi) : "l"(acc[i][p]));
            int a0 = tx * 8 + p * 2;
            sres[i] += su2[a0]     * tanhf(lo + sb2[a0]);
            sres[i] += su2[a0 + 1] * tanhf(hi + sb2[a0 + 1]);
        }
    }
#pragma unroll
    for (int i = 0; i < 8; i++) sp[ty * 8 + i][tx] = sres[i];
    __syncthreads();
    if (tid < 128) {
        float s = 0.f;
#pragma unroll
        for (int xx = 0; xx < 16; xx++) s += sp[tid][xx];
        g_s2[(t0 + tid) * BATCH + b] = s;
    }
}

// =============================================================================
// K4: softmax over T, attention pool, linear head.  One CTA per batch.
// =============================================================================
__global__ __launch_bounds__(256) void k4_final(const float* __restrict__ Wl,
                                                const float* __restrict__ bl,
                                                float* __restrict__ out) {
    __shared__ float a2s[T_STEPS];
    __shared__ float red[256];
    const int b = blockIdx.x, tid = threadIdx.x;

    for (int t = tid; t < T_STEPS; t += 256)
        a2s[t] = expf(g_s2[t * BATCH + b]);
    __syncthreads();

    float p = a2s[tid] + a2s[tid + 256];
    red[tid] = p;
    __syncthreads();
#pragma unroll
    for (int o = 128; o > 0; o >>= 1) {
        if (tid < o) red[tid] += red[tid + o];
        __syncthreads();
    }
    const float inv = 1.f / red[0];
    __syncthreads();

    float acc = 0.f;
    const float* hp = g_hs + (size_t)b * HID + tid;
#pragma unroll 8
    for (int t = 0; t < T_STEPS; t++)
        acc += a2s[t] * hp[(size_t)t * BATCH * HID];
    acc *= inv;

    float v = acc * Wl[tid];
    red[tid] = v;
    __syncthreads();
#pragma unroll
    for (int o = 128; o > 0; o >>= 1) {
        if (tid < o) red[tid] += red[tid + o];
        __syncthreads();
    }
    if (tid == 0) out[b] = red[0] + bl[0];
}

// =============================================================================
// launcher
// =============================================================================
extern "C" void kernel_launch(void* const* d_in, const int* in_sizes, int n_in,
                              void* d_out, int out_size) {
    const float* inputs = (const float*)d_in[0];
    const float* W1  = (const float*)d_in[1];
    const float* b1  = (const float*)d_in[2];
    const float* u1  = (const float*)d_in[3];
    const float* Wih = (const float*)d_in[4];
    const float* Whh = (const float*)d_in[5];
    const float* bih = (const float*)d_in[6];
    const float* bhh = (const float*)d_in[7];
    const float* h0  = (const float*)d_in[8];
    const float* c0  = (const float*)d_in[9];
    const float* W2  = (const float*)d_in[10];
    const float* b2  = (const float*)d_in[11];
    const float* u2  = (const float*)d_in[12];
    const float* Wl  = (const float*)d_in[13];
    const float* bl  = (const float*)d_in[14];
    float* out = (float*)d_out;

    k0_lut  <<<33, 256>>>(W1, b1, u1);
    k1_att1 <<<512, 256>>>(inputs);
    k_nop   <<<1, 32>>>();            // keeps ncu capture slot on k2
    k2_lstm <<<64, NTHR>>>(Whh, Wih, bih, bhh, h0, c0);
    k3_att2 <<<128, 256>>>(W2, b2, u2);
    k4_final<<<32, 256>>>(Wl, bl, out);
}